// round 3
// baseline (speedup 1.0000x reference)
#include <cuda_runtime.h>
#include <cuda_bf16.h>
#include <math.h>
#include <stdint.h>

// Problem constants
#define BB 32
#define TT 32
#define AD 32
#define HID 1536
#define K2 (2*HID)   // 3072

// Scratch (__device__ globals, allocation-free rule)
__device__ __nv_bfloat16 g_xhi[BB*TT*K2];
__device__ __nv_bfloat16 g_xlo[BB*TT*K2];
__device__ __nv_bfloat16 g_hhi[BB*TT*HID];
__device__ __nv_bfloat16 g_hlo[BB*TT*HID];
__device__ int g_gcat[32];
__device__ int g_gsamp[32][4];
__device__ int g_ngroups;

// ---------------------------------------------------------------------------
// Setup: group samples by cat (chunks of 4)
// ---------------------------------------------------------------------------
__global__ void setup_groups(const int* __restrict__ cats)
{
    int n = 0;
    for (int c = 0; c < 32; c++) {
        int list[32]; int cnt = 0;
        for (int s = 0; s < BB; s++) if (cats[s] == c) list[cnt++] = s;
        for (int base = 0; base < cnt; base += 4) {
            g_gcat[n] = c;
            for (int j = 0; j < 4; j++)
                g_gsamp[n][j] = (base + j < cnt) ? list[base + j] : -1;
            n++;
        }
    }
    g_ngroups = n;
    for (int s = n; s < 32; s++) {
        g_gcat[s] = -1;
        for (int j = 0; j < 4; j++) g_gsamp[s][j] = -1;
    }
}

// ---------------------------------------------------------------------------
// helpers
// ---------------------------------------------------------------------------
__device__ __forceinline__ uint32_t split_pack_hi(float v0, float v1, uint32_t& lo) {
    __nv_bfloat16 h0 = __float2bfloat16_rn(v0);
    __nv_bfloat16 h1 = __float2bfloat16_rn(v1);
    __nv_bfloat162 hp; hp.x = h0; hp.y = h1;
    __nv_bfloat162 lp = __floats2bfloat162_rn(v0 - __bfloat162float(h0),
                                              v1 - __bfloat162float(h1));
    lo = *reinterpret_cast<uint32_t*>(&lp);
    return *reinterpret_cast<uint32_t*>(&hp);
}

// ---------------------------------------------------------------------------
// Kernel 1: x = [actions @ W1[cat] + b1, sinusoidal(ts)] -> bf16 hi/lo
// one block per (b,t); threads handle (sin,cos) pairs
// ---------------------------------------------------------------------------
__global__ __launch_bounds__(256) void embed_kernel(
    const float* __restrict__ actions,
    const int*   __restrict__ timesteps,
    const int*   __restrict__ cats,
    const float* __restrict__ W1,
    const float* __restrict__ b1)
{
    int bt = blockIdx.x;
    int b  = bt >> 5;
    __shared__ float sa[AD];
    if (threadIdx.x < AD) sa[threadIdx.x] = actions[bt*AD + threadIdx.x];
    __syncthreads();

    int cat = cats[b];
    const float* Wc = W1 + (size_t)cat * AD * HID;
    const float* bc = b1 + (size_t)cat * HID;
    float ts = (float)timesteps[b];
    size_t rowoff = (size_t)bt * K2;

    const float C = -9.210340371976184f / 768.0f;   // -ln(1e4)/half

    #pragma unroll
    for (int pp = 0; pp < 3; pp++) {
        int p = pp*256 + threadIdx.x;   // pair index 0..767
        int j = 2*p;

        // a_emb: two dot products
        float2 bb = *reinterpret_cast<const float2*>(&bc[j]);
        float acc0 = bb.x, acc1 = bb.y;
        #pragma unroll
        for (int k = 0; k < AD; k++) {
            float2 w = *reinterpret_cast<const float2*>(&Wc[(size_t)k*HID + j]);
            acc0 += sa[k]*w.x;
            acc1 += sa[k]*w.y;
        }
        uint32_t lo, hi;
        hi = split_pack_hi(acc0, acc1, lo);
        *reinterpret_cast<uint32_t*>(&g_xhi[rowoff + j]) = hi;
        *reinterpret_cast<uint32_t*>(&g_xlo[rowoff + j]) = lo;

        // tau: sin/cos pair, freq index = p
        float freq = expf(C * (float)p);
        float arg = ts * freq;
        float s, c;
        sincosf(arg, &s, &c);
        hi = split_pack_hi(s, c, lo);
        *reinterpret_cast<uint32_t*>(&g_xhi[rowoff + HID + j]) = hi;
        *reinterpret_cast<uint32_t*>(&g_xlo[rowoff + HID + j]) = lo;
    }
}

// ---------------------------------------------------------------------------
// Grouped tensor-core GEMM: out = act( X @ W[cat] + bias[cat] )
// CTA: M=128 (4 samples of one cat) x N=128, K-tile 32
// 8 warps: msub = w&3 (one sample, 32 rows), nhalf = w>>2 (64 cols)
// X pre-split bf16 hi/lo in gmem (cp.async copy); W fp32 converted in staging.
// ---------------------------------------------------------------------------
#define PADX 40    // 80B row stride: conflict-free ldmatrix
#define PADW 136   // 272B row stride: conflict-free ldmatrix

#define MMA_BF16(d, a0,a1,a2,a3, b0,b1) \
  asm volatile("mma.sync.aligned.m16n8k16.row.col.f32.bf16.bf16.f32 " \
               "{%0,%1,%2,%3}, {%4,%5,%6,%7}, {%8,%9}, {%0,%1,%2,%3};" \
               : "+f"(d[0]),"+f"(d[1]),"+f"(d[2]),"+f"(d[3]) \
               : "r"(a0),"r"(a1),"r"(a2),"r"(a3),"r"(b0),"r"(b1))

#define LDSM_X4(r0,r1,r2,r3, addr) \
  asm volatile("ldmatrix.sync.aligned.m8n8.x4.shared.b16 {%0,%1,%2,%3}, [%4];" \
               : "=r"(r0),"=r"(r1),"=r"(r2),"=r"(r3) : "r"(addr))

#define LDSM_X2T(r0,r1, addr) \
  asm volatile("ldmatrix.sync.aligned.m8n8.x2.trans.shared.b16 {%0,%1}, [%2];" \
               : "=r"(r0),"=r"(r1) : "r"(addr))

#define CP_ASYNC8(saddr, gaddr, sz) \
  asm volatile("cp.async.ca.shared.global [%0], [%1], 8, %2;" \
               :: "r"(saddr), "l"(gaddr), "r"(sz))

__global__ __launch_bounds__(256,2) void gemm_grouped(
    const __nv_bfloat16* __restrict__ Xhi,
    const __nv_bfloat16* __restrict__ Xlo,
    const float* __restrict__ W,
    const float* __restrict__ bias,
    float* __restrict__ Yf32,            // used if !writeH
    int K, int writeH)
{
    if ((int)blockIdx.y >= g_ngroups) return;

    __shared__ __nv_bfloat16 sXhi[128*PADX], sXlo[128*PADX];
    __shared__ __nv_bfloat16 sWhi[32*PADW],  sWlo[32*PADW];

    int slot = blockIdx.y;
    int cat  = g_gcat[slot];
    int samp[4];
    #pragma unroll
    for (int j = 0; j < 4; j++) samp[j] = g_gsamp[slot][j];

    int n0 = blockIdx.x * 128;
    const float* Wc = W + (size_t)cat * K * HID;

    int tid  = threadIdx.x;
    int lane = tid & 31;
    int warp = tid >> 5;
    int msub = warp & 3;           // sample slot within group
    int nhalf = warp >> 2;         // 0/1: cols nhalf*64..+63
    bool active = (samp[msub] >= 0);
    int myrow0 = samp[msub] * 32;  // global X row base for this warp (if active)

    int lr15 = lane & 15;
    int hiK8 = ((lane >> 4) & 1) * 8;

    float acc[2][8][4];
    #pragma unroll
    for (int mt = 0; mt < 2; mt++)
        #pragma unroll
        for (int nt = 0; nt < 8; nt++)
            #pragma unroll
            for (int j = 0; j < 4; j++) acc[mt][nt][j] = 0.0f;

    uint32_t aXhi = (uint32_t)__cvta_generic_to_shared(sXhi);
    uint32_t aXlo = (uint32_t)__cvta_generic_to_shared(sXlo);
    uint32_t aWhi = (uint32_t)__cvta_generic_to_shared(sWhi);
    uint32_t aWlo = (uint32_t)__cvta_generic_to_shared(sWlo);

    // X staging geometry: tile 128 rows x 32 k; 8B chunks of 4 bf16.
    // chunk idx = c*256 + tid (c=0..3): row = idx>>3, q = idx&7 -> k = q*4
    int xrow[4], xq[4], xsz[4];
    const __nv_bfloat16* xsrc_base[4];
    #pragma unroll
    for (int c = 0; c < 4; c++) {
        int idx = c*256 + tid;
        int row = idx >> 3, q = idx & 7;
        xrow[c] = row; xq[c] = q;
        int sp = samp[row >> 5];
        xsz[c] = (sp >= 0) ? 8 : 0;
        xsrc_base[c] = (sp >= 0)
            ? (Xhi + (size_t)(sp*32 + (row & 31))*K + q*4)   // offset by k0 and hi/lo later
            : Xhi;  // dummy (size 0)
    }

    // W prefetch regs (k0 = 0)
    float4 wreg[4];
    #pragma unroll
    for (int i = 0; i < 4; i++) {
        int idx = i*256 + tid;
        int kr = idx >> 5, c4 = idx & 31;
        wreg[i] = *reinterpret_cast<const float4*>(&Wc[(size_t)kr*HID + n0 + c4*4]);
    }

    size_t xlo_delta = (size_t)(Xlo - Xhi);   // element delta between arrays

    #pragma unroll 1
    for (int k0 = 0; k0 < K; k0 += 32) {
        // ---- cp.async: X tile (bf16 hi/lo, no conversion) ----
        #pragma unroll
        for (int c = 0; c < 4; c++) {
            uint32_t soff = (uint32_t)((xrow[c]*PADX + xq[c]*4) * 2);
            const __nv_bfloat16* gh = xsrc_base[c] + k0;
            CP_ASYNC8(aXhi + soff, gh, xsz[c]);
            CP_ASYNC8(aXlo + soff, gh + xlo_delta, xsz[c]);
        }
        asm volatile("cp.async.commit_group;" ::: "memory");

        // ---- stage W: fp32 -> bf16 hi/lo from prefetched regs ----
        #pragma unroll
        for (int i = 0; i < 4; i++) {
            int idx = i*256 + tid;
            int kr = idx >> 5, c4 = idx & 31;
            uint2 hv, lv;
            hv.x = split_pack_hi(wreg[i].x, wreg[i].y, lv.x);
            hv.y = split_pack_hi(wreg[i].z, wreg[i].w, lv.y);
            *reinterpret_cast<uint2*>(&sWhi[kr*PADW + c4*4]) = hv;
            *reinterpret_cast<uint2*>(&sWlo[kr*PADW + c4*4]) = lv;
        }

        // ---- prefetch next W tile ----
        if (k0 + 32 < K) {
            #pragma unroll
            for (int i = 0; i < 4; i++) {
                int idx = i*256 + tid;
                int kr = idx >> 5, c4 = idx & 31;
                wreg[i] = *reinterpret_cast<const float4*>(
                    &Wc[(size_t)(k0 + 32 + kr)*HID + n0 + c4*4]);
            }
        }

        asm volatile("cp.async.wait_group 0;" ::: "memory");
        __syncthreads();

        // ---- compute ----
        if (active) {
            #pragma unroll
            for (int ks = 0; ks < 2; ks++) {
                uint32_t ah[2][4], al[2][4];
                #pragma unroll
                for (int mt = 0; mt < 2; mt++) {
                    uint32_t aoff = (uint32_t)((((msub*32 + mt*16 + lr15)*PADX)
                                                + ks*16 + hiK8) * 2);
                    LDSM_X4(ah[mt][0],ah[mt][1],ah[mt][2],ah[mt][3], aXhi + aoff);
                    LDSM_X4(al[mt][0],al[mt][1],al[mt][2],al[mt][3], aXlo + aoff);
                }
                #pragma unroll
                for (int nt = 0; nt < 8; nt++) {
                    uint32_t boff = (uint32_t)((((ks*16 + lr15)*PADW)
                                                + (nhalf*8 + nt)*8) * 2);
                    uint32_t bh0,bh1, bl0,bl1;
                    LDSM_X2T(bh0,bh1, aWhi + boff);
                    LDSM_X2T(bl0,bl1, aWlo + boff);
                    #pragma unroll
                    for (int mt = 0; mt < 2; mt++) {
                        MMA_BF16(acc[mt][nt], ah[mt][0],ah[mt][1],ah[mt][2],ah[mt][3], bh0,bh1);
                        MMA_BF16(acc[mt][nt], ah[mt][0],ah[mt][1],ah[mt][2],ah[mt][3], bl0,bl1);
                        MMA_BF16(acc[mt][nt], al[mt][0],al[mt][1],al[mt][2],al[mt][3], bh0,bh1);
                    }
                }
            }
        }
        __syncthreads();
    }

    // ---- epilogue ----
    if (!active) return;
    int r  = lane >> 2;
    int c2 = (lane & 3) * 2;
    #pragma unroll
    for (int mt = 0; mt < 2; mt++) {
        #pragma unroll
        for (int nt = 0; nt < 8; nt++) {
            int col = n0 + (nhalf*8 + nt)*8 + c2;
            float2 bv = *reinterpret_cast<const float2*>(&bias[(size_t)cat*HID + col]);
            float y0 = acc[mt][nt][0] + bv.x;
            float y1 = acc[mt][nt][1] + bv.y;
            float y2 = acc[mt][nt][2] + bv.x;
            float y3 = acc[mt][nt][3] + bv.y;
            int row0 = myrow0 + mt*16 + r;      // global row
            if (writeH) {
                // swish then split to bf16 hi/lo
                y0 = y0 / (1.0f + __expf(-y0));
                y1 = y1 / (1.0f + __expf(-y1));
                y2 = y2 / (1.0f + __expf(-y2));
                y3 = y3 / (1.0f + __expf(-y3));
                uint32_t lo, hi;
                hi = split_pack_hi(y0, y1, lo);
                *reinterpret_cast<uint32_t*>(&g_hhi[(size_t)row0*HID + col]) = hi;
                *reinterpret_cast<uint32_t*>(&g_hlo[(size_t)row0*HID + col]) = lo;
                hi = split_pack_hi(y2, y3, lo);
                *reinterpret_cast<uint32_t*>(&g_hhi[(size_t)(row0+8)*HID + col]) = hi;
                *reinterpret_cast<uint32_t*>(&g_hlo[(size_t)(row0+8)*HID + col]) = lo;
            } else {
                float2 o01 = {y0, y1};
                float2 o23 = {y2, y3};
                *reinterpret_cast<float2*>(&Yf32[(size_t)row0*HID + col]) = o01;
                *reinterpret_cast<float2*>(&Yf32[(size_t)(row0+8)*HID + col]) = o23;
            }
        }
    }
}

// ---------------------------------------------------------------------------
extern "C" void kernel_launch(void* const* d_in, const int* in_sizes, int n_in,
                              void* d_out, int out_size)
{
    const float* actions   = (const float*)d_in[0];
    const int*   timesteps = (const int*)  d_in[1];
    const int*   cat_ids   = (const int*)  d_in[2];
    const float* W1        = (const float*)d_in[3];
    const float* b1        = (const float*)d_in[4];
    const float* W2        = (const float*)d_in[5];
    const float* b2        = (const float*)d_in[6];
    const float* W3        = (const float*)d_in[7];
    const float* b3        = (const float*)d_in[8];
    float* out = (float*)d_out;

    __nv_bfloat16 *xh, *xl, *hh, *hl;
    cudaGetSymbolAddress((void**)&xh, g_xhi);
    cudaGetSymbolAddress((void**)&xl, g_xlo);
    cudaGetSymbolAddress((void**)&hh, g_hhi);
    cudaGetSymbolAddress((void**)&hl, g_hlo);

    setup_groups<<<1, 1>>>(cat_ids);
    embed_kernel<<<BB*TT, 256>>>(actions, timesteps, cat_ids, W1, b1);

    // h = swish(x @ W2[cat] + b2)  -> bf16 hi/lo
    gemm_grouped<<<dim3(HID/128, 32), 256>>>(xh, xl, W2, b2, nullptr, K2, 1);

    // out = h @ W3[cat] + b3       -> fp32
    gemm_grouped<<<dim3(HID/128, 32), 256>>>(hh, hl, W3, b3, out, HID, 0);
}

// round 4
// speedup vs baseline: 1.0774x; 1.0774x over previous
#include <cuda_runtime.h>
#include <cuda_bf16.h>
#include <math.h>
#include <stdint.h>

// Problem constants
#define BB 32
#define TT 32
#define AD 32
#define HID 1536
#define K2 (2*HID)   // 3072

// Scratch (__device__ globals, allocation-free rule)
__device__ __nv_bfloat16 g_xhi[BB*TT*K2];
__device__ __nv_bfloat16 g_xlo[BB*TT*K2];
__device__ __nv_bfloat16 g_hhi[BB*TT*HID];
__device__ __nv_bfloat16 g_hlo[BB*TT*HID];
__device__ int g_gcat[32];
__device__ int g_gsamp[32][4];
__device__ int g_ngroups;

// ---------------------------------------------------------------------------
// Setup: group samples by cat (chunks of 4). One warp, ~2us.
// ---------------------------------------------------------------------------
__global__ void setup_groups(const int* __restrict__ cats)
{
    __shared__ int sc[32];
    int t = threadIdx.x;              // t = cat id 0..31
    sc[t] = cats[t];
    __syncwarp();

    unsigned mask = 0;
    #pragma unroll
    for (int s = 0; s < 32; s++)
        if (sc[s] == t) mask |= (1u << s);
    int cnt = __popc(mask);
    int ng  = (cnt + 3) >> 2;

    // warp inclusive scan -> exclusive prefix
    int incl = ng;
    #pragma unroll
    for (int off = 1; off < 32; off <<= 1) {
        int v = __shfl_up_sync(0xffffffffu, incl, off);
        if (t >= off) incl += v;
    }
    int pre   = incl - ng;
    int total = __shfl_sync(0xffffffffu, incl, 31);
    if (t == 0) g_ngroups = total;

    unsigned m = mask;
    for (int g = 0; g < ng; g++) {
        int slot = pre + g;
        g_gcat[slot] = t;
        #pragma unroll
        for (int j = 0; j < 4; j++) {
            int s = -1;
            if (m) { s = __ffs(m) - 1; m &= m - 1; }
            g_gsamp[slot][j] = s;
        }
    }
    for (int slot = total + t; slot < 32; slot += 32) {
        g_gcat[slot] = -1;
        #pragma unroll
        for (int j = 0; j < 4; j++) g_gsamp[slot][j] = -1;
    }
}

// ---------------------------------------------------------------------------
// helpers
// ---------------------------------------------------------------------------
__device__ __forceinline__ uint32_t split_pack_hi(float v0, float v1, uint32_t& lo) {
    __nv_bfloat16 h0 = __float2bfloat16_rn(v0);
    __nv_bfloat16 h1 = __float2bfloat16_rn(v1);
    __nv_bfloat162 hp; hp.x = h0; hp.y = h1;
    __nv_bfloat162 lp = __floats2bfloat162_rn(v0 - __bfloat162float(h0),
                                              v1 - __bfloat162float(h1));
    lo = *reinterpret_cast<uint32_t*>(&lp);
    return *reinterpret_cast<uint32_t*>(&hp);
}

// ---------------------------------------------------------------------------
// Kernel 1: x = [actions @ W1[cat] + b1, sinusoidal(ts)] -> bf16 hi/lo
// grid (B, 3); block 256; thread owns col pair j=2p for all T rows
// W1[cat] col slice read once per (b, chunk) -> ~6 MB total traffic
// ---------------------------------------------------------------------------
__global__ __launch_bounds__(256) void embed_kernel(
    const float* __restrict__ actions,
    const int*   __restrict__ timesteps,
    const int*   __restrict__ cats,
    const float* __restrict__ W1,
    const float* __restrict__ b1)
{
    int b = blockIdx.x;
    int p = blockIdx.y * 256 + threadIdx.x;  // pair idx 0..767
    int j = 2 * p;

    __shared__ float sa[TT*AD];
    for (int i = threadIdx.x; i < TT*AD; i += 256)
        sa[i] = actions[(size_t)b*TT*AD + i];
    __syncthreads();

    int cat = cats[b];
    const float* Wc = W1 + (size_t)cat * AD * HID;
    float2 bb = *reinterpret_cast<const float2*>(&b1[(size_t)cat*HID + j]);

    float2 wv[AD];
    #pragma unroll
    for (int k = 0; k < AD; k++)
        wv[k] = *reinterpret_cast<const float2*>(&Wc[(size_t)k*HID + j]);

    // tau pair (same for all t of this b)
    const float C = -9.210340371976184f / 768.0f;
    float ts = (float)timesteps[b];
    float freq = expf(C * (float)p);
    float s, c;
    sincosf(ts * freq, &s, &c);
    uint32_t tlo, thi = split_pack_hi(s, c, tlo);

    #pragma unroll 4
    for (int t = 0; t < TT; t++) {
        float a0 = bb.x, a1 = bb.y;
        #pragma unroll
        for (int k = 0; k < AD; k++) {
            float av = sa[t*AD + k];
            a0 += av * wv[k].x;
            a1 += av * wv[k].y;
        }
        size_t row = (size_t)(b*TT + t) * K2;
        uint32_t lo, hi = split_pack_hi(a0, a1, lo);
        *reinterpret_cast<uint32_t*>(&g_xhi[row + j]) = hi;
        *reinterpret_cast<uint32_t*>(&g_xlo[row + j]) = lo;
        *reinterpret_cast<uint32_t*>(&g_xhi[row + HID + j]) = thi;
        *reinterpret_cast<uint32_t*>(&g_xlo[row + HID + j]) = tlo;
    }
}

// ---------------------------------------------------------------------------
// Grouped tensor-core GEMM, double-buffered.
// CTA: M=128 (4 samples, one cat) x N=128, K-tile 32, ping-pong smem.
// ---------------------------------------------------------------------------
#define PADX 40    // 80B row stride: conflict-free ldmatrix
#define PADW 136   // 272B row stride: conflict-free ldmatrix
#define XBUF (128*PADX)
#define WBUF (32*PADW)
#define SMEM_ELEMS (2*2*XBUF + 2*2*WBUF)
#define SMEM_BYTES (SMEM_ELEMS*2)

#define MMA_BF16(d, a0,a1,a2,a3, b0,b1) \
  asm volatile("mma.sync.aligned.m16n8k16.row.col.f32.bf16.bf16.f32 " \
               "{%0,%1,%2,%3}, {%4,%5,%6,%7}, {%8,%9}, {%0,%1,%2,%3};" \
               : "+f"(d[0]),"+f"(d[1]),"+f"(d[2]),"+f"(d[3]) \
               : "r"(a0),"r"(a1),"r"(a2),"r"(a3),"r"(b0),"r"(b1))

#define LDSM_X4(r0,r1,r2,r3, addr) \
  asm volatile("ldmatrix.sync.aligned.m8n8.x4.shared.b16 {%0,%1,%2,%3}, [%4];" \
               : "=r"(r0),"=r"(r1),"=r"(r2),"=r"(r3) : "r"(addr))

#define LDSM_X2T(r0,r1, addr) \
  asm volatile("ldmatrix.sync.aligned.m8n8.x2.trans.shared.b16 {%0,%1}, [%2];" \
               : "=r"(r0),"=r"(r1) : "r"(addr))

#define CP_ASYNC8(saddr, gaddr, sz) \
  asm volatile("cp.async.ca.shared.global [%0], [%1], 8, %2;" \
               :: "r"(saddr), "l"(gaddr), "r"(sz))

__global__ __launch_bounds__(256,2) void gemm_grouped(
    const __nv_bfloat16* __restrict__ Xhi,
    const __nv_bfloat16* __restrict__ Xlo,
    const float* __restrict__ W,
    const float* __restrict__ bias,
    float* __restrict__ Yf32,
    int K, int writeH)
{
    if ((int)blockIdx.y >= g_ngroups) return;

    extern __shared__ __nv_bfloat16 smem[];
    __nv_bfloat16* sXhi = smem;                    // [2][XBUF]
    __nv_bfloat16* sXlo = sXhi + 2*XBUF;
    __nv_bfloat16* sWhi = sXlo + 2*XBUF;           // [2][WBUF]
    __nv_bfloat16* sWlo = sWhi + 2*WBUF;

    int slot = blockIdx.y;
    int cat  = g_gcat[slot];
    int samp[4];
    #pragma unroll
    for (int j = 0; j < 4; j++) samp[j] = g_gsamp[slot][j];

    int n0 = blockIdx.x * 128;
    const float* Wc = W + (size_t)cat * K * HID;

    int tid  = threadIdx.x;
    int lane = tid & 31;
    int warp = tid >> 5;
    int msub = warp & 3;
    int nhalf = warp >> 2;
    bool active = (samp[msub] >= 0);
    int myrow0 = samp[msub] * 32;

    int lr15 = lane & 15;
    int hiK8 = ((lane >> 4) & 1) * 8;

    float acc[2][8][4];
    #pragma unroll
    for (int mt = 0; mt < 2; mt++)
        #pragma unroll
        for (int nt = 0; nt < 8; nt++)
            #pragma unroll
            for (int j = 0; j < 4; j++) acc[mt][nt][j] = 0.0f;

    uint32_t aXhi = (uint32_t)__cvta_generic_to_shared(sXhi);
    uint32_t aXlo = (uint32_t)__cvta_generic_to_shared(sXlo);
    uint32_t aWhi = (uint32_t)__cvta_generic_to_shared(sWhi);
    uint32_t aWlo = (uint32_t)__cvta_generic_to_shared(sWlo);

    // X staging geometry: 128 rows x 32 k, 8B chunks (4 bf16)
    int xrow[4], xq[4], xsz[4];
    const __nv_bfloat16* xsrc_base[4];
    #pragma unroll
    for (int c = 0; c < 4; c++) {
        int idx = c*256 + tid;
        int row = idx >> 3, q = idx & 7;
        xrow[c] = row; xq[c] = q;
        int sp = samp[row >> 5];
        xsz[c] = (sp >= 0) ? 8 : 0;
        xsrc_base[c] = (sp >= 0)
            ? (Xhi + (size_t)(sp*32 + (row & 31))*K + q*4)
            : Xhi;
    }
    size_t xlo_delta = (size_t)(Xlo - Xhi);

    // W staging geometry
    int wkr[4], wc4[4];
    #pragma unroll
    for (int i = 0; i < 4; i++) {
        int idx = i*256 + tid;
        wkr[i] = idx >> 5; wc4[i] = idx & 31;
    }

    int nt_tiles = K >> 5;
    float4 wreg[4];

    // ---- prologue: tile 0 ----
    #pragma unroll
    for (int i = 0; i < 4; i++)
        wreg[i] = *reinterpret_cast<const float4*>(&Wc[(size_t)wkr[i]*HID + n0 + wc4[i]*4]);
    #pragma unroll
    for (int i = 0; i < 4; i++) {
        uint2 hv, lv;
        hv.x = split_pack_hi(wreg[i].x, wreg[i].y, lv.x);
        hv.y = split_pack_hi(wreg[i].z, wreg[i].w, lv.y);
        *reinterpret_cast<uint2*>(&sWhi[wkr[i]*PADW + wc4[i]*4]) = hv;
        *reinterpret_cast<uint2*>(&sWlo[wkr[i]*PADW + wc4[i]*4]) = lv;
    }
    #pragma unroll
    for (int c = 0; c < 4; c++) {
        uint32_t soff = (uint32_t)((xrow[c]*PADX + xq[c]*4) * 2);
        CP_ASYNC8(aXhi + soff, xsrc_base[c], xsz[c]);
        CP_ASYNC8(aXlo + soff, xsrc_base[c] + xlo_delta, xsz[c]);
    }
    asm volatile("cp.async.commit_group;" ::: "memory");
    // prefetch W tile 1
    #pragma unroll
    for (int i = 0; i < 4; i++)
        wreg[i] = *reinterpret_cast<const float4*>(&Wc[(size_t)(32 + wkr[i])*HID + n0 + wc4[i]*4]);
    asm volatile("cp.async.wait_group 0;" ::: "memory");
    __syncthreads();

    #pragma unroll 1
    for (int it = 0; it < nt_tiles; it++) {
        int bi  = it & 1;
        int nx  = bi ^ 1;
        int k0n = (it + 1) << 5;

        if (it + 1 < nt_tiles) {
            // cp.async X(it+1) into next buffer
            #pragma unroll
            for (int c = 0; c < 4; c++) {
                uint32_t soff = (uint32_t)(((nx*128 + xrow[c])*PADX + xq[c]*4) * 2);
                const __nv_bfloat16* gh = xsrc_base[c] + k0n;
                CP_ASYNC8(aXhi + soff, gh, xsz[c]);
                CP_ASYNC8(aXlo + soff, gh + xlo_delta, xsz[c]);
            }
            asm volatile("cp.async.commit_group;" ::: "memory");
            // convert W(it+1) from regs into next buffer
            #pragma unroll
            for (int i = 0; i < 4; i++) {
                uint2 hv, lv;
                hv.x = split_pack_hi(wreg[i].x, wreg[i].y, lv.x);
                hv.y = split_pack_hi(wreg[i].z, wreg[i].w, lv.y);
                *reinterpret_cast<uint2*>(&sWhi[(nx*32 + wkr[i])*PADW + wc4[i]*4]) = hv;
                *reinterpret_cast<uint2*>(&sWlo[(nx*32 + wkr[i])*PADW + wc4[i]*4]) = lv;
            }
            // prefetch W(it+2)
            if (it + 2 < nt_tiles) {
                int k0nn = (it + 2) << 5;
                #pragma unroll
                for (int i = 0; i < 4; i++)
                    wreg[i] = *reinterpret_cast<const float4*>(
                        &Wc[(size_t)(k0nn + wkr[i])*HID + n0 + wc4[i]*4]);
            }
        }

        // ---- compute on buffer bi ----
        if (active) {
            #pragma unroll
            for (int ks = 0; ks < 2; ks++) {
                uint32_t ah[2][4], al[2][4];
                #pragma unroll
                for (int mt = 0; mt < 2; mt++) {
                    uint32_t aoff = (uint32_t)((((bi*128 + msub*32 + mt*16 + lr15)*PADX)
                                                + ks*16 + hiK8) * 2);
                    LDSM_X4(ah[mt][0],ah[mt][1],ah[mt][2],ah[mt][3], aXhi + aoff);
                    LDSM_X4(al[mt][0],al[mt][1],al[mt][2],al[mt][3], aXlo + aoff);
                }
                #pragma unroll
                for (int nt = 0; nt < 8; nt++) {
                    uint32_t boff = (uint32_t)((((bi*32 + ks*16 + lr15)*PADW)
                                                + (nhalf*8 + nt)*8) * 2);
                    uint32_t bh0,bh1, bl0,bl1;
                    LDSM_X2T(bh0,bh1, aWhi + boff);
                    LDSM_X2T(bl0,bl1, aWlo + boff);
                    #pragma unroll
                    for (int mt = 0; mt < 2; mt++) {
                        MMA_BF16(acc[mt][nt], ah[mt][0],ah[mt][1],ah[mt][2],ah[mt][3], bh0,bh1);
                        MMA_BF16(acc[mt][nt], ah[mt][0],ah[mt][1],ah[mt][2],ah[mt][3], bl0,bl1);
                        MMA_BF16(acc[mt][nt], al[mt][0],al[mt][1],al[mt][2],al[mt][3], bh0,bh1);
                    }
                }
            }
        }

        if (it + 1 < nt_tiles) {
            asm volatile("cp.async.wait_group 0;" ::: "memory");
            __syncthreads();
        }
    }

    // ---- epilogue ----
    if (!active) return;
    int r  = lane >> 2;
    int c2 = (lane & 3) * 2;
    #pragma unroll
    for (int mt = 0; mt < 2; mt++) {
        #pragma unroll
        for (int nt = 0; nt < 8; nt++) {
            int col = n0 + (nhalf*8 + nt)*8 + c2;
            float2 bv = *reinterpret_cast<const float2*>(&bias[(size_t)cat*HID + col]);
            float y0 = acc[mt][nt][0] + bv.x;
            float y1 = acc[mt][nt][1] + bv.y;
            float y2 = acc[mt][nt][2] + bv.x;
            float y3 = acc[mt][nt][3] + bv.y;
            int row0 = myrow0 + mt*16 + r;
            if (writeH) {
                y0 = y0 / (1.0f + __expf(-y0));
                y1 = y1 / (1.0f + __expf(-y1));
                y2 = y2 / (1.0f + __expf(-y2));
                y3 = y3 / (1.0f + __expf(-y3));
                uint32_t lo, hi;
                hi = split_pack_hi(y0, y1, lo);
                *reinterpret_cast<uint32_t*>(&g_hhi[(size_t)row0*HID + col]) = hi;
                *reinterpret_cast<uint32_t*>(&g_hlo[(size_t)row0*HID + col]) = lo;
                hi = split_pack_hi(y2, y3, lo);
                *reinterpret_cast<uint32_t*>(&g_hhi[(size_t)(row0+8)*HID + col]) = hi;
                *reinterpret_cast<uint32_t*>(&g_hlo[(size_t)(row0+8)*HID + col]) = lo;
            } else {
                float2 o01 = {y0, y1};
                float2 o23 = {y2, y3};
                *reinterpret_cast<float2*>(&Yf32[(size_t)row0*HID + col]) = o01;
                *reinterpret_cast<float2*>(&Yf32[(size_t)(row0+8)*HID + col]) = o23;
            }
        }
    }
}

// ---------------------------------------------------------------------------
extern "C" void kernel_launch(void* const* d_in, const int* in_sizes, int n_in,
                              void* d_out, int out_size)
{
    const float* actions   = (const float*)d_in[0];
    const int*   timesteps = (const int*)  d_in[1];
    const int*   cat_ids   = (const int*)  d_in[2];
    const float* W1        = (const float*)d_in[3];
    const float* b1        = (const float*)d_in[4];
    const float* W2        = (const float*)d_in[5];
    const float* b2        = (const float*)d_in[6];
    const float* W3        = (const float*)d_in[7];
    const float* b3        = (const float*)d_in[8];
    float* out = (float*)d_out;

    __nv_bfloat16 *xh, *xl, *hh, *hl;
    cudaGetSymbolAddress((void**)&xh, g_xhi);
    cudaGetSymbolAddress((void**)&xl, g_xlo);
    cudaGetSymbolAddress((void**)&hh, g_hhi);
    cudaGetSymbolAddress((void**)&hl, g_hlo);

    static bool attr_set = false;
    if (!attr_set) {
        cudaFuncSetAttribute(gemm_grouped,
                             cudaFuncAttributeMaxDynamicSharedMemorySize, SMEM_BYTES);
        attr_set = true;
    }

    setup_groups<<<1, 32>>>(cat_ids);
    embed_kernel<<<dim3(BB, 3), 256>>>(actions, timesteps, cat_ids, W1, b1);

    // h = swish(x @ W2[cat] + b2)  -> bf16 hi/lo
    gemm_grouped<<<dim3(HID/128, 32), 256, SMEM_BYTES>>>(xh, xl, W2, b2, nullptr, K2, 1);

    // out = h @ W3[cat] + b3       -> fp32
    gemm_grouped<<<dim3(HID/128, 32), 256, SMEM_BYTES>>>(hh, hl, W3, b3, out, HID, 0);
}

// round 5
// speedup vs baseline: 1.0827x; 1.0050x over previous
#include <cuda_runtime.h>
#include <cuda_bf16.h>
#include <math.h>
#include <stdint.h>

// Problem constants
#define BB 32
#define TT 32
#define AD 32
#define HID 1536
#define K2 (2*HID)   // 3072

// Scratch (__device__ globals, allocation-free rule)
__device__ __nv_bfloat16 g_xhi[BB*TT*K2];
__device__ __nv_bfloat16 g_xlo[BB*TT*K2];
__device__ __nv_bfloat16 g_hhi[BB*TT*HID];
__device__ __nv_bfloat16 g_hlo[BB*TT*HID];
__device__ int g_gcat[32];
__device__ int g_gsamp[32][4];
__device__ int g_ngroups;

// ---------------------------------------------------------------------------
// Setup: group samples by cat (chunks of 4). One warp.
// ---------------------------------------------------------------------------
__global__ void setup_groups(const int* __restrict__ cats)
{
    __shared__ int sc[32];
    int t = threadIdx.x;
    sc[t] = cats[t];
    __syncwarp();

    unsigned mask = 0;
    #pragma unroll
    for (int s = 0; s < 32; s++)
        if (sc[s] == t) mask |= (1u << s);
    int cnt = __popc(mask);
    int ng  = (cnt + 3) >> 2;

    int incl = ng;
    #pragma unroll
    for (int off = 1; off < 32; off <<= 1) {
        int v = __shfl_up_sync(0xffffffffu, incl, off);
        if (t >= off) incl += v;
    }
    int pre   = incl - ng;
    int total = __shfl_sync(0xffffffffu, incl, 31);
    if (t == 0) g_ngroups = total;

    unsigned m = mask;
    for (int g = 0; g < ng; g++) {
        int slot = pre + g;
        g_gcat[slot] = t;
        #pragma unroll
        for (int j = 0; j < 4; j++) {
            int s = -1;
            if (m) { s = __ffs(m) - 1; m &= m - 1; }
            g_gsamp[slot][j] = s;
        }
    }
    for (int slot = total + t; slot < 32; slot += 32) {
        g_gcat[slot] = -1;
        #pragma unroll
        for (int j = 0; j < 4; j++) g_gsamp[slot][j] = -1;
    }
}

// ---------------------------------------------------------------------------
__device__ __forceinline__ uint32_t split_pack_hi(float v0, float v1, uint32_t& lo) {
    __nv_bfloat16 h0 = __float2bfloat16_rn(v0);
    __nv_bfloat16 h1 = __float2bfloat16_rn(v1);
    __nv_bfloat162 hp; hp.x = h0; hp.y = h1;
    __nv_bfloat162 lp = __floats2bfloat162_rn(v0 - __bfloat162float(h0),
                                              v1 - __bfloat162float(h1));
    lo = *reinterpret_cast<uint32_t*>(&lp);
    return *reinterpret_cast<uint32_t*>(&hp);
}

// ---------------------------------------------------------------------------
// Kernel 1: x = [actions @ W1[cat] + b1, sinusoidal(ts)] -> bf16 hi/lo
// ---------------------------------------------------------------------------
__global__ __launch_bounds__(256) void embed_kernel(
    const float* __restrict__ actions,
    const int*   __restrict__ timesteps,
    const int*   __restrict__ cats,
    const float* __restrict__ W1,
    const float* __restrict__ b1)
{
    int b = blockIdx.x;
    int p = blockIdx.y * 256 + threadIdx.x;
    int j = 2 * p;

    __shared__ float sa[TT*AD];
    for (int i = threadIdx.x; i < TT*AD; i += 256)
        sa[i] = actions[(size_t)b*TT*AD + i];
    __syncthreads();

    int cat = cats[b];
    const float* Wc = W1 + (size_t)cat * AD * HID;
    float2 bb = *reinterpret_cast<const float2*>(&b1[(size_t)cat*HID + j]);

    float2 wv[AD];
    #pragma unroll
    for (int k = 0; k < AD; k++)
        wv[k] = *reinterpret_cast<const float2*>(&Wc[(size_t)k*HID + j]);

    const float C = -9.210340371976184f / 768.0f;
    float ts = (float)timesteps[b];
    float freq = expf(C * (float)p);
    float s, c;
    sincosf(ts * freq, &s, &c);
    uint32_t tlo, thi = split_pack_hi(s, c, tlo);

    #pragma unroll 4
    for (int t = 0; t < TT; t++) {
        float a0 = bb.x, a1 = bb.y;
        #pragma unroll
        for (int k = 0; k < AD; k++) {
            float av = sa[t*AD + k];
            a0 += av * wv[k].x;
            a1 += av * wv[k].y;
        }
        size_t row = (size_t)(b*TT + t) * K2;
        uint32_t lo, hi = split_pack_hi(a0, a1, lo);
        *reinterpret_cast<uint32_t*>(&g_xhi[row + j]) = hi;
        *reinterpret_cast<uint32_t*>(&g_xlo[row + j]) = lo;
        *reinterpret_cast<uint32_t*>(&g_xhi[row + HID + j]) = thi;
        *reinterpret_cast<uint32_t*>(&g_xlo[row + HID + j]) = tlo;
    }
}

// ---------------------------------------------------------------------------
// Grouped tensor-core GEMM, deep cp.async pipeline.
// CTA: M=128 (4 samples, one cat) x N=64, K-tile 32.
// 3-stage rings for X(bf16 hi/lo) and W(fp32); W converted smem->smem per tile.
// Group g_i = {X(i+2), W(i+2)} committed at iter i; wait_group 1 => depth 2.
// ---------------------------------------------------------------------------
#define TN    64
#define PADX  40      // X row stride (elems): conflict-free ldmatrix
#define PADW  72      // Wbf16 row stride (elems): 144B, conflict-free
#define XELEM (128*PADX)          // 5120 per stage per array
#define WF32  (32*TN)             // 2048 floats per stage
#define WCONV (32*PADW)           // 2304 bf16 per array

// bytes: X 2*3*5120*2=61440, Wf32 3*2048*4=24576, Wconv 2*2304*2=9216
#define SMEM_BYTES (61440 + 24576 + 9216)

#define MMA_BF16(d, a0,a1,a2,a3, b0,b1) \
  asm volatile("mma.sync.aligned.m16n8k16.row.col.f32.bf16.bf16.f32 " \
               "{%0,%1,%2,%3}, {%4,%5,%6,%7}, {%8,%9}, {%0,%1,%2,%3};" \
               : "+f"(d[0]),"+f"(d[1]),"+f"(d[2]),"+f"(d[3]) \
               : "r"(a0),"r"(a1),"r"(a2),"r"(a3),"r"(b0),"r"(b1))

#define LDSM_X4(r0,r1,r2,r3, addr) \
  asm volatile("ldmatrix.sync.aligned.m8n8.x4.shared.b16 {%0,%1,%2,%3}, [%4];" \
               : "=r"(r0),"=r"(r1),"=r"(r2),"=r"(r3) : "r"(addr))

#define LDSM_X2T(r0,r1, addr) \
  asm volatile("ldmatrix.sync.aligned.m8n8.x2.trans.shared.b16 {%0,%1}, [%2];" \
               : "=r"(r0),"=r"(r1) : "r"(addr))

#define CP_ASYNC8(saddr, gaddr, sz) \
  asm volatile("cp.async.ca.shared.global [%0], [%1], 8, %2;" \
               :: "r"(saddr), "l"(gaddr), "r"(sz))

#define CP_ASYNC16(saddr, gaddr) \
  asm volatile("cp.async.ca.shared.global [%0], [%1], 16;" \
               :: "r"(saddr), "l"(gaddr))

__global__ __launch_bounds__(256,2) void gemm_grouped(
    const __nv_bfloat16* __restrict__ Xhi,
    const __nv_bfloat16* __restrict__ Xlo,
    const float* __restrict__ W,
    const float* __restrict__ bias,
    float* __restrict__ Yf32,
    int K, int writeH)
{
    if ((int)blockIdx.y >= g_ngroups) return;

    extern __shared__ __nv_bfloat16 smem[];
    __nv_bfloat16* sXhi = smem;                       // [3][XELEM]
    __nv_bfloat16* sXlo = sXhi + 3*XELEM;             // [3][XELEM]
    float*         sWf  = (float*)(sXlo + 3*XELEM);   // [3][WF32]
    __nv_bfloat16* sWhi = (__nv_bfloat16*)(sWf + 3*WF32);  // [WCONV]
    __nv_bfloat16* sWlo = sWhi + WCONV;

    int slot = blockIdx.y;
    int cat  = g_gcat[slot];
    int samp[4];
    #pragma unroll
    for (int j = 0; j < 4; j++) samp[j] = g_gsamp[slot][j];

    int n0 = blockIdx.x * TN;
    const float* Wc = W + (size_t)cat * K * HID;

    int tid  = threadIdx.x;
    int lane = tid & 31;
    int warp = tid >> 5;
    int msub = warp & 3;
    int nhalf = warp >> 2;
    bool active = (samp[msub] >= 0);
    int myrow0 = samp[msub] * 32;

    int lr15 = lane & 15;
    int hiK8 = ((lane >> 4) & 1) * 8;

    float acc[2][4][4];
    #pragma unroll
    for (int mt = 0; mt < 2; mt++)
        #pragma unroll
        for (int nt = 0; nt < 4; nt++)
            #pragma unroll
            for (int j = 0; j < 4; j++) acc[mt][nt][j] = 0.0f;

    uint32_t aXhi = (uint32_t)__cvta_generic_to_shared(sXhi);
    uint32_t aXlo = (uint32_t)__cvta_generic_to_shared(sXlo);
    uint32_t aWf  = (uint32_t)__cvta_generic_to_shared(sWf);
    uint32_t aWhi = (uint32_t)__cvta_generic_to_shared(sWhi);
    uint32_t aWlo = (uint32_t)__cvta_generic_to_shared(sWlo);

    // X staging: 128 rows x 32 k, 8B chunks. chunk idx = c*256+tid: row=idx>>3, q=idx&7
    int xrow[4], xq[4], xsz[4];
    const __nv_bfloat16* xsrc[4];
    #pragma unroll
    for (int c = 0; c < 4; c++) {
        int idx = c*256 + tid;
        int row = idx >> 3, q = idx & 7;
        xrow[c] = row; xq[c] = q;
        int sp = samp[row >> 5];
        xsz[c] = (sp >= 0) ? 8 : 0;
        xsrc[c] = (sp >= 0) ? (Xhi + (size_t)(sp*32 + (row & 31))*K + q*4) : Xhi;
    }
    size_t xlo_delta = (size_t)(Xlo - Xhi);

    // W staging: 32 k-rows x 64 cols fp32, 16B chunks: idx=c*256+tid: kr=idx>>4, c4=idx&15
    int wkr[2], wc4[2];
    #pragma unroll
    for (int c = 0; c < 2; c++) {
        int idx = c*256 + tid;
        wkr[c] = idx >> 4; wc4[c] = idx & 15;
    }

    int NT = K >> 5;

    // ---- prologue: issue tiles 0 and 1 ----
    #pragma unroll
    for (int pi = 0; pi < 2; pi++) {
        #pragma unroll
        for (int c = 0; c < 4; c++) {
            uint32_t soff = (uint32_t)((pi*XELEM + xrow[c]*PADX + xq[c]*4) * 2);
            const __nv_bfloat16* gh = xsrc[c] + pi*32;
            CP_ASYNC8(aXhi + soff, gh, xsz[c]);
            CP_ASYNC8(aXlo + soff, gh + xlo_delta, xsz[c]);
        }
        #pragma unroll
        for (int c = 0; c < 2; c++) {
            uint32_t soff = (uint32_t)((pi*WF32 + wkr[c]*TN + wc4[c]*4) * 4);
            CP_ASYNC16(aWf + soff, &Wc[(size_t)(pi*32 + wkr[c])*HID + n0 + wc4[c]*4]);
        }
        asm volatile("cp.async.commit_group;" ::: "memory");
    }

    #pragma unroll 1
    for (int it = 0; it < NT; it++) {
        int bi = it % 3;

        // wait: all groups except the newest (tail: wait all)
        if (it < NT - 1) {
            asm volatile("cp.async.wait_group 1;" ::: "memory");
        } else {
            asm volatile("cp.async.wait_group 0;" ::: "memory");
        }
        __syncthreads();   // X(it), Wf32(it) visible; Wconv free

        // issue tile it+2
        if (it + 2 < NT) {
            int nx = (it + 2) % 3;
            int k0n = (it + 2) << 5;
            #pragma unroll
            for (int c = 0; c < 4; c++) {
                uint32_t soff = (uint32_t)((nx*XELEM + xrow[c]*PADX + xq[c]*4) * 2);
                const __nv_bfloat16* gh = xsrc[c] + k0n;
                CP_ASYNC8(aXhi + soff, gh, xsz[c]);
                CP_ASYNC8(aXlo + soff, gh + xlo_delta, xsz[c]);
            }
            #pragma unroll
            for (int c = 0; c < 2; c++) {
                uint32_t soff = (uint32_t)((nx*WF32 + wkr[c]*TN + wc4[c]*4) * 4);
                CP_ASYNC16(aWf + soff, &Wc[(size_t)(k0n + wkr[c])*HID + n0 + wc4[c]*4]);
            }
            asm volatile("cp.async.commit_group;" ::: "memory");
        }

        // convert W(it): fp32 smem -> bf16 hi/lo smem
        #pragma unroll
        for (int c = 0; c < 2; c++) {
            float4 v = *reinterpret_cast<const float4*>(&sWf[bi*WF32 + wkr[c]*TN + wc4[c]*4]);
            uint2 hv, lv;
            hv.x = split_pack_hi(v.x, v.y, lv.x);
            hv.y = split_pack_hi(v.z, v.w, lv.y);
            *reinterpret_cast<uint2*>(&sWhi[wkr[c]*PADW + wc4[c]*4]) = hv;
            *reinterpret_cast<uint2*>(&sWlo[wkr[c]*PADW + wc4[c]*4]) = lv;
        }
        __syncthreads();   // Wconv ready

        // compute tile it
        if (active) {
            #pragma unroll
            for (int ks = 0; ks < 2; ks++) {
                uint32_t ah[2][4], al[2][4];
                #pragma unroll
                for (int mt = 0; mt < 2; mt++) {
                    uint32_t aoff = (uint32_t)((bi*XELEM
                        + (msub*32 + mt*16 + lr15)*PADX + ks*16 + hiK8) * 2);
                    LDSM_X4(ah[mt][0],ah[mt][1],ah[mt][2],ah[mt][3], aXhi + aoff);
                    LDSM_X4(al[mt][0],al[mt][1],al[mt][2],al[mt][3], aXlo + aoff);
                }
                #pragma unroll
                for (int nt = 0; nt < 4; nt++) {
                    uint32_t boff = (uint32_t)(((ks*16 + lr15)*PADW
                        + nhalf*32 + nt*8) * 2);
                    uint32_t bh0,bh1, bl0,bl1;
                    LDSM_X2T(bh0,bh1, aWhi + boff);
                    LDSM_X2T(bl0,bl1, aWlo + boff);
                    #pragma unroll
                    for (int mt = 0; mt < 2; mt++) {
                        MMA_BF16(acc[mt][nt], ah[mt][0],ah[mt][1],ah[mt][2],ah[mt][3], bh0,bh1);
                        MMA_BF16(acc[mt][nt], ah[mt][0],ah[mt][1],ah[mt][2],ah[mt][3], bl0,bl1);
                        MMA_BF16(acc[mt][nt], al[mt][0],al[mt][1],al[mt][2],al[mt][3], bh0,bh1);
                    }
                }
            }
        }
    }

    // ---- epilogue ----
    if (!active) return;
    int r  = lane >> 2;
    int c2 = (lane & 3) * 2;
    #pragma unroll
    for (int mt = 0; mt < 2; mt++) {
        #pragma unroll
        for (int nt = 0; nt < 4; nt++) {
            int col = n0 + nhalf*32 + nt*8 + c2;
            float2 bv = *reinterpret_cast<const float2*>(&bias[(size_t)cat*HID + col]);
            float y0 = acc[mt][nt][0] + bv.x;
            float y1 = acc[mt][nt][1] + bv.y;
            float y2 = acc[mt][nt][2] + bv.x;
            float y3 = acc[mt][nt][3] + bv.y;
            int row0 = myrow0 + mt*16 + r;
            if (writeH) {
                y0 = y0 / (1.0f + __expf(-y0));
                y1 = y1 / (1.0f + __expf(-y1));
                y2 = y2 / (1.0f + __expf(-y2));
                y3 = y3 / (1.0f + __expf(-y3));
                uint32_t lo, hi;
                hi = split_pack_hi(y0, y1, lo);
                *reinterpret_cast<uint32_t*>(&g_hhi[(size_t)row0*HID + col]) = hi;
                *reinterpret_cast<uint32_t*>(&g_hlo[(size_t)row0*HID + col]) = lo;
                hi = split_pack_hi(y2, y3, lo);
                *reinterpret_cast<uint32_t*>(&g_hhi[(size_t)(row0+8)*HID + col]) = hi;
                *reinterpret_cast<uint32_t*>(&g_hlo[(size_t)(row0+8)*HID + col]) = lo;
            } else {
                float2 o01 = {y0, y1};
                float2 o23 = {y2, y3};
                *reinterpret_cast<float2*>(&Yf32[(size_t)row0*HID + col]) = o01;
                *reinterpret_cast<float2*>(&Yf32[(size_t)(row0+8)*HID + col]) = o23;
            }
        }
    }
}

// ---------------------------------------------------------------------------
extern "C" void kernel_launch(void* const* d_in, const int* in_sizes, int n_in,
                              void* d_out, int out_size)
{
    const float* actions   = (const float*)d_in[0];
    const int*   timesteps = (const int*)  d_in[1];
    const int*   cat_ids   = (const int*)  d_in[2];
    const float* W1        = (const float*)d_in[3];
    const float* b1        = (const float*)d_in[4];
    const float* W2        = (const float*)d_in[5];
    const float* b2        = (const float*)d_in[6];
    const float* W3        = (const float*)d_in[7];
    const float* b3        = (const float*)d_in[8];
    float* out = (float*)d_out;

    __nv_bfloat16 *xh, *xl, *hh, *hl;
    cudaGetSymbolAddress((void**)&xh, g_xhi);
    cudaGetSymbolAddress((void**)&xl, g_xlo);
    cudaGetSymbolAddress((void**)&hh, g_hhi);
    cudaGetSymbolAddress((void**)&hl, g_hlo);

    static bool attr_set = false;
    if (!attr_set) {
        cudaFuncSetAttribute(gemm_grouped,
                             cudaFuncAttributeMaxDynamicSharedMemorySize, SMEM_BYTES);
        attr_set = true;
    }

    setup_groups<<<1, 32>>>(cat_ids);
    embed_kernel<<<dim3(BB, 3), 256>>>(actions, timesteps, cat_ids, W1, b1);

    // h = swish(x @ W2[cat] + b2)  -> bf16 hi/lo
    gemm_grouped<<<dim3(HID/TN, 32), 256, SMEM_BYTES>>>(xh, xl, W2, b2, nullptr, K2, 1);

    // out = h @ W3[cat] + b3       -> fp32
    gemm_grouped<<<dim3(HID/TN, 32), 256, SMEM_BYTES>>>(hh, hl, W3, b3, out, HID, 0);
}

// round 7
// speedup vs baseline: 1.8735x; 1.7303x over previous
#include <cuda_runtime.h>
#include <cuda_fp16.h>
#include <math.h>
#include <stdint.h>

// Problem constants
#define BB 32
#define TT 32
#define AD 32
#define HID 1536
#define K2 (2*HID)   // 3072

// Scratch (__device__ globals)
__device__ __half g_xf[BB*TT*K2];    // concat([a_emb, tau]) fp16
__device__ __half g_hf[BB*TT*HID];   // swish hidden fp16
__device__ int g_gcat[32];
__device__ int g_gsamp[32][2];
__device__ int g_ngroups;

// ---------------------------------------------------------------------------
// Setup: group samples by cat in pairs. One warp.
// ---------------------------------------------------------------------------
__global__ void setup_groups(const int* __restrict__ cats)
{
    __shared__ int sc[32];
    int t = threadIdx.x;
    sc[t] = cats[t];
    __syncwarp();

    unsigned mask = 0;
    #pragma unroll
    for (int s = 0; s < 32; s++)
        if (sc[s] == t) mask |= (1u << s);
    int cnt = __popc(mask);
    int ng  = (cnt + 1) >> 1;

    int incl = ng;
    #pragma unroll
    for (int off = 1; off < 32; off <<= 1) {
        int v = __shfl_up_sync(0xffffffffu, incl, off);
        if (t >= off) incl += v;
    }
    int pre   = incl - ng;
    int total = __shfl_sync(0xffffffffu, incl, 31);
    if (t == 0) g_ngroups = total;

    unsigned m = mask;
    for (int g = 0; g < ng; g++) {
        int slot = pre + g;
        g_gcat[slot] = t;
        #pragma unroll
        for (int j = 0; j < 2; j++) {
            int s = -1;
            if (m) { s = __ffs(m) - 1; m &= m - 1; }
            g_gsamp[slot][j] = s;
        }
    }
    for (int slot = total + t; slot < 32; slot += 32) {
        g_gcat[slot] = -1;
        g_gsamp[slot][0] = -1;
        g_gsamp[slot][1] = -1;
    }
}

// ---------------------------------------------------------------------------
// Kernel 1: x = [actions @ W1[cat] + b1, sinusoidal(ts)] -> fp16
// ---------------------------------------------------------------------------
__global__ __launch_bounds__(256) void embed_kernel(
    const float* __restrict__ actions,
    const int*   __restrict__ timesteps,
    const int*   __restrict__ cats,
    const float* __restrict__ W1,
    const float* __restrict__ b1)
{
    int b = blockIdx.x;
    int p = blockIdx.y * 256 + threadIdx.x;   // pair idx 0..767
    int j = 2 * p;

    __shared__ float sa[TT*AD];
    for (int i = threadIdx.x; i < TT*AD; i += 256)
        sa[i] = actions[(size_t)b*TT*AD + i];
    __syncthreads();

    int cat = cats[b];
    const float* Wc = W1 + (size_t)cat * AD * HID;
    float2 bb = *reinterpret_cast<const float2*>(&b1[(size_t)cat*HID + j]);

    float2 wv[AD];
    #pragma unroll
    for (int k = 0; k < AD; k++)
        wv[k] = *reinterpret_cast<const float2*>(&Wc[(size_t)k*HID + j]);

    const float C = -9.210340371976184f / 768.0f;
    float ts = (float)timesteps[b];
    float freq = expf(C * (float)p);
    float s, c;
    sincosf(ts * freq, &s, &c);
    __half2 tp = __floats2half2_rn(s, c);
    uint32_t tu = *reinterpret_cast<uint32_t*>(&tp);

    #pragma unroll 4
    for (int t = 0; t < TT; t++) {
        float a0 = bb.x, a1 = bb.y;
        #pragma unroll
        for (int k = 0; k < AD; k++) {
            float av = sa[t*AD + k];
            a0 += av * wv[k].x;
            a1 += av * wv[k].y;
        }
        size_t row = (size_t)(b*TT + t) * K2;
        __half2 ap = __floats2half2_rn(a0, a1);
        *reinterpret_cast<uint32_t*>(&g_xf[row + j]) = *reinterpret_cast<uint32_t*>(&ap);
        *reinterpret_cast<uint32_t*>(&g_xf[row + HID + j]) = tu;
    }
}

// ---------------------------------------------------------------------------
// Grouped fp16 tensor-core GEMM, single-pass precision.
// CTA: M=64 (2 samples, one cat) x N=128, K-tile 32. 8 warps.
// Warp w exclusively owns N-cols [w*16, w*16+16): converts its own W slice
// fp32->fp16 warp-privately. One __syncthreads per tile.
// 3-stage cp.async rings: X fp16, W fp32.
// ---------------------------------------------------------------------------
#define GM    64
#define GN    128
#define PADX  40                 // X fp16 row stride
#define WFS   132                // W fp32 row stride (pad vs 128)
#define PADW  136                // W fp16 row stride (272B, covers 128 cols, conflict-free)
#define XELEM (GM*PADX)          // 2560 fp16 / stage
#define WF32S (32*WFS)           // 4224 fp32 / stage
#define WCONV (32*PADW)          // 4352 fp16
// bytes: X 3*2560*2=15360, Wf32 3*4224*4=50688, Wconv 4352*2=8704
#define SMEM_BYTES (3*XELEM*2 + 3*WF32S*4 + WCONV*2)   // 74752

#define MMA_F16(d, a0,a1,a2,a3, b0,b1) \
  asm volatile("mma.sync.aligned.m16n8k16.row.col.f32.f16.f16.f32 " \
               "{%0,%1,%2,%3}, {%4,%5,%6,%7}, {%8,%9}, {%0,%1,%2,%3};" \
               : "+f"(d[0]),"+f"(d[1]),"+f"(d[2]),"+f"(d[3]) \
               : "r"(a0),"r"(a1),"r"(a2),"r"(a3),"r"(b0),"r"(b1))

#define LDSM_X4(r0,r1,r2,r3, addr) \
  asm volatile("ldmatrix.sync.aligned.m8n8.x4.shared.b16 {%0,%1,%2,%3}, [%4];" \
               : "=r"(r0),"=r"(r1),"=r"(r2),"=r"(r3) : "r"(addr))

#define LDSM_X2T(r0,r1, addr) \
  asm volatile("ldmatrix.sync.aligned.m8n8.x2.trans.shared.b16 {%0,%1}, [%2];" \
               : "=r"(r0),"=r"(r1) : "r"(addr))

#define CP_ASYNC8(saddr, gaddr, sz) \
  asm volatile("cp.async.ca.shared.global [%0], [%1], 8, %2;" \
               :: "r"(saddr), "l"(gaddr), "r"(sz))

#define CP_ASYNC16(saddr, gaddr) \
  asm volatile("cp.async.ca.shared.global [%0], [%1], 16;" \
               :: "r"(saddr), "l"(gaddr))

__global__ __launch_bounds__(256,3) void gemm_grouped(
    const __half* __restrict__ Xf,
    const float* __restrict__ W,
    const float* __restrict__ bias,
    float* __restrict__ Yf32,
    int K, int writeH)
{
    if ((int)blockIdx.y >= g_ngroups) return;

    extern __shared__ __half smem[];
    __half* sX = smem;                                 // [3][XELEM]
    float*  sWf = (float*)(sX + 3*XELEM);              // [3][WF32S]
    __half* sWc = (__half*)(sWf + 3*WF32S);            // [WCONV]

    int slot = blockIdx.y;
    int cat  = g_gcat[slot];
    int s0 = g_gsamp[slot][0];
    int s1 = g_gsamp[slot][1];

    int n0 = blockIdx.x * GN;
    const float* Wc = W + (size_t)cat * K * HID;

    int tid  = threadIdx.x;
    int lane = tid & 31;
    int warp = tid >> 5;

    int lr15 = lane & 15;
    int hiK8 = ((lane >> 4) & 1) * 8;

    float acc[4][2][4];
    #pragma unroll
    for (int mt = 0; mt < 4; mt++)
        #pragma unroll
        for (int nt = 0; nt < 2; nt++)
            #pragma unroll
            for (int j = 0; j < 4; j++) acc[mt][nt][j] = 0.0f;

    uint32_t aX  = (uint32_t)__cvta_generic_to_shared(sX);
    uint32_t aWf = (uint32_t)__cvta_generic_to_shared(sWf);
    uint32_t aWc = (uint32_t)__cvta_generic_to_shared(sWc);

    // X staging: 64 rows x 32 k fp16, 8B chunks; 2 per thread
    int xrow[2], xq[2], xsz[2];
    const __half* xsrc[2];
    #pragma unroll
    for (int c = 0; c < 2; c++) {
        int idx = c*256 + tid;
        int row = idx >> 3, q = idx & 7;
        xrow[c] = row; xq[c] = q;
        int sp = (row < 32) ? s0 : s1;
        xsz[c] = (sp >= 0) ? 8 : 0;
        xsrc[c] = (sp >= 0) ? (Xf + (size_t)(sp*32 + (row & 31))*K + q*4) : Xf;
    }

    // W staging: 32 k x 128 n fp32, 16B chunks; 4 per thread
    int wkr[4], wc4[4];
    #pragma unroll
    for (int c = 0; c < 4; c++) {
        int idx = c*256 + tid;
        wkr[c] = idx >> 5; wc4[c] = idx & 31;
    }

    int NT = K >> 5;

    // ---- prologue: tiles 0, 1 ----
    #pragma unroll
    for (int pi = 0; pi < 2; pi++) {
        #pragma unroll
        for (int c = 0; c < 2; c++) {
            uint32_t soff = (uint32_t)((pi*XELEM + xrow[c]*PADX + xq[c]*4) * 2);
            CP_ASYNC8(aX + soff, xsrc[c] + pi*32, xsz[c]);
        }
        #pragma unroll
        for (int c = 0; c < 4; c++) {
            uint32_t soff = (uint32_t)((pi*WF32S + wkr[c]*WFS + wc4[c]*4) * 4);
            CP_ASYNC16(aWf + soff, &Wc[(size_t)(pi*32 + wkr[c])*HID + n0 + wc4[c]*4]);
        }
        asm volatile("cp.async.commit_group;" ::: "memory");
    }

    #pragma unroll 1
    for (int it = 0; it < NT; it++) {
        int bi = it % 3;

        if (it < NT - 1)
            asm volatile("cp.async.wait_group 1;" ::: "memory");
        else
            asm volatile("cp.async.wait_group 0;" ::: "memory");
        __syncthreads();

        // issue tile it+2
        if (it + 2 < NT) {
            int nx = (it + 2) % 3;
            int k0n = (it + 2) << 5;
            #pragma unroll
            for (int c = 0; c < 2; c++) {
                uint32_t soff = (uint32_t)((nx*XELEM + xrow[c]*PADX + xq[c]*4) * 2);
                CP_ASYNC8(aX + soff, xsrc[c] + k0n, xsz[c]);
            }
            #pragma unroll
            for (int c = 0; c < 4; c++) {
                uint32_t soff = (uint32_t)((nx*WF32S + wkr[c]*WFS + wc4[c]*4) * 4);
                CP_ASYNC16(aWf + soff, &Wc[(size_t)(k0n + wkr[c])*HID + n0 + wc4[c]*4]);
            }
            asm volatile("cp.async.commit_group;" ::: "memory");
        }

        // convert own 16 N-cols: lane = k-row, warp-private region
        {
            const float* wrow = &sWf[bi*WF32S + lane*WFS + warp*16];
            __half* crow = &sWc[lane*PADW + warp*16];
            #pragma unroll
            for (int jj = 0; jj < 4; jj++) {
                float4 v = *reinterpret_cast<const float4*>(wrow + jj*4);
                __half2 p0 = __floats2half2_rn(v.x, v.y);
                __half2 p1 = __floats2half2_rn(v.z, v.w);
                uint2 u;
                u.x = *reinterpret_cast<uint32_t*>(&p0);
                u.y = *reinterpret_cast<uint32_t*>(&p1);
                *reinterpret_cast<uint2*>(crow + jj*4) = u;
            }
        }
        __syncwarp();

        // compute tile it
        #pragma unroll
        for (int ks = 0; ks < 2; ks++) {
            uint32_t a[4][4];
            #pragma unroll
            for (int mt = 0; mt < 4; mt++) {
                uint32_t aoff = (uint32_t)((bi*XELEM
                    + (mt*16 + lr15)*PADX + ks*16 + hiK8) * 2);
                LDSM_X4(a[mt][0],a[mt][1],a[mt][2],a[mt][3], aX + aoff);
            }
            #pragma unroll
            for (int nt = 0; nt < 2; nt++) {
                uint32_t boff = (uint32_t)(((ks*16 + lr15)*PADW + warp*16 + nt*8) * 2);
                uint32_t b0, b1;
                LDSM_X2T(b0, b1, aWc + boff);
                #pragma unroll
                for (int mt = 0; mt < 4; mt++)
                    MMA_F16(acc[mt][nt], a[mt][0],a[mt][1],a[mt][2],a[mt][3], b0,b1);
            }
        }
    }

    // ---- epilogue ----
    int r  = lane >> 2;
    int c2 = (lane & 3) * 2;
    #pragma unroll
    for (int mt = 0; mt < 4; mt++) {
        int lrow0 = mt*16 + r;              // local rows lrow0, lrow0+8
        int sp = (lrow0 < 32) ? s0 : s1;    // both rows in same 32-row half
        if (sp < 0) continue;
        int grow0 = sp*32 + (lrow0 & 31);
        #pragma unroll
        for (int nt = 0; nt < 2; nt++) {
            int col = n0 + warp*16 + nt*8 + c2;
            float2 bv = *reinterpret_cast<const float2*>(&bias[(size_t)cat*HID + col]);
            float y0 = acc[mt][nt][0] + bv.x;
            float y1 = acc[mt][nt][1] + bv.y;
            float y2 = acc[mt][nt][2] + bv.x;
            float y3 = acc[mt][nt][3] + bv.y;
            if (writeH) {
                y0 = y0 / (1.0f + __expf(-y0));
                y1 = y1 / (1.0f + __expf(-y1));
                y2 = y2 / (1.0f + __expf(-y2));
                y3 = y3 / (1.0f + __expf(-y3));
                __half2 p01 = __floats2half2_rn(y0, y1);
                __half2 p23 = __floats2half2_rn(y2, y3);
                *reinterpret_cast<uint32_t*>(&g_hf[(size_t)grow0*HID + col])
                    = *reinterpret_cast<uint32_t*>(&p01);
                *reinterpret_cast<uint32_t*>(&g_hf[(size_t)(grow0+8)*HID + col])
                    = *reinterpret_cast<uint32_t*>(&p23);
            } else {
                float2 o01 = {y0, y1};
                float2 o23 = {y2, y3};
                *reinterpret_cast<float2*>(&Yf32[(size_t)grow0*HID + col]) = o01;
                *reinterpret_cast<float2*>(&Yf32[(size_t)(grow0+8)*HID + col]) = o23;
            }
        }
    }
}

// ---------------------------------------------------------------------------
extern "C" void kernel_launch(void* const* d_in, const int* in_sizes, int n_in,
                              void* d_out, int out_size)
{
    const float* actions   = (const float*)d_in[0];
    const int*   timesteps = (const int*)  d_in[1];
    const int*   cat_ids   = (const int*)  d_in[2];
    const float* W1        = (const float*)d_in[3];
    const float* b1        = (const float*)d_in[4];
    const float* W2        = (const float*)d_in[5];
    const float* b2        = (const float*)d_in[6];
    const float* W3        = (const float*)d_in[7];
    const float* b3        = (const float*)d_in[8];
    float* out = (float*)d_out;

    __half *xf, *hf;
    cudaGetSymbolAddress((void**)&xf, g_xf);
    cudaGetSymbolAddress((void**)&hf, g_hf);

    static bool attr_set = false;
    if (!attr_set) {
        cudaFuncSetAttribute(gemm_grouped,
                             cudaFuncAttributeMaxDynamicSharedMemorySize, SMEM_BYTES);
        attr_set = true;
    }

    setup_groups<<<1, 32>>>(cat_ids);
    embed_kernel<<<dim3(BB, 3), 256>>>(actions, timesteps, cat_ids, W1, b1);

    // h = swish(x @ W2[cat] + b2) -> fp16
    gemm_grouped<<<dim3(HID/GN, 32), 256, SMEM_BYTES>>>(xf, W2, b2, nullptr, K2, 1);

    // out = h @ W3[cat] + b3 -> fp32
    gemm_grouped<<<dim3(HID/GN, 32), 256, SMEM_BYTES>>>(hf, W3, b3, out, HID, 0);
}

// round 9
// speedup vs baseline: 2.2520x; 1.2021x over previous
#include <cuda_runtime.h>
#include <cuda_fp16.h>
#include <math.h>
#include <stdint.h>

// Problem constants
#define BB 32
#define TT 32
#define AD 32
#define HID 1536
#define K2 (2*HID)   // 3072

// Scratch (__device__ globals)
__device__ __half g_xf[BB*TT*K2];    // concat([a_emb, tau]) fp16
__device__ __half g_hf[BB*TT*HID];   // swish hidden fp16
__device__ int g_gcat[32];
__device__ int g_gsamp[32][2];
__device__ int g_ngroups;

// ---------------------------------------------------------------------------
// Setup: group samples by cat in pairs. One warp.
// ---------------------------------------------------------------------------
__global__ void setup_groups(const int* __restrict__ cats)
{
    __shared__ int sc[32];
    int t = threadIdx.x;
    sc[t] = cats[t];
    __syncwarp();

    unsigned mask = 0;
    #pragma unroll
    for (int s = 0; s < 32; s++)
        if (sc[s] == t) mask |= (1u << s);
    int cnt = __popc(mask);
    int ng  = (cnt + 1) >> 1;

    int incl = ng;
    #pragma unroll
    for (int off = 1; off < 32; off <<= 1) {
        int v = __shfl_up_sync(0xffffffffu, incl, off);
        if (t >= off) incl += v;
    }
    int pre   = incl - ng;
    int total = __shfl_sync(0xffffffffu, incl, 31);
    if (t == 0) g_ngroups = total;

    unsigned m = mask;
    for (int g = 0; g < ng; g++) {
        int slot = pre + g;
        g_gcat[slot] = t;
        #pragma unroll
        for (int j = 0; j < 2; j++) {
            int s = -1;
            if (m) { s = __ffs(m) - 1; m &= m - 1; }
            g_gsamp[slot][j] = s;
        }
    }
    for (int slot = total + t; slot < 32; slot += 32) {
        g_gcat[slot] = -1;
        g_gsamp[slot][0] = -1;
        g_gsamp[slot][1] = -1;
    }
}

// ---------------------------------------------------------------------------
// Kernel 1: x = [actions @ W1[cat] + b1, sinusoidal(ts)] -> fp16
// ---------------------------------------------------------------------------
__global__ __launch_bounds__(256) void embed_kernel(
    const float* __restrict__ actions,
    const int*   __restrict__ timesteps,
    const int*   __restrict__ cats,
    const float* __restrict__ W1,
    const float* __restrict__ b1)
{
    int b = blockIdx.x;
    int p = blockIdx.y * 256 + threadIdx.x;
    int j = 2 * p;

    __shared__ float sa[TT*AD];
    for (int i = threadIdx.x; i < TT*AD; i += 256)
        sa[i] = actions[(size_t)b*TT*AD + i];
    __syncthreads();

    int cat = cats[b];
    const float* Wc = W1 + (size_t)cat * AD * HID;
    float2 bb = *reinterpret_cast<const float2*>(&b1[(size_t)cat*HID + j]);

    float2 wv[AD];
    #pragma unroll
    for (int k = 0; k < AD; k++)
        wv[k] = *reinterpret_cast<const float2*>(&Wc[(size_t)k*HID + j]);

    const float C = -9.210340371976184f / 768.0f;
    float ts = (float)timesteps[b];
    float freq = expf(C * (float)p);
    float s, c;
    sincosf(ts * freq, &s, &c);
    __half2 tp = __floats2half2_rn(s, c);
    uint32_t tu = *reinterpret_cast<uint32_t*>(&tp);

    #pragma unroll 4
    for (int t = 0; t < TT; t++) {
        float a0 = bb.x, a1 = bb.y;
        #pragma unroll
        for (int k = 0; k < AD; k++) {
            float av = sa[t*AD + k];
            a0 += av * wv[k].x;
            a1 += av * wv[k].y;
        }
        size_t row = (size_t)(b*TT + t) * K2;
        __half2 ap = __floats2half2_rn(a0, a1);
        *reinterpret_cast<uint32_t*>(&g_xf[row + j]) = *reinterpret_cast<uint32_t*>(&ap);
        *reinterpret_cast<uint32_t*>(&g_xf[row + HID + j]) = tu;
    }
}

// ---------------------------------------------------------------------------
// Grouped fp16 mma.sync GEMM.
// CTA: M=64 (2 samples, one cat) x N=64, K-tile 32. 8 warps, warp = 32r x 16c
//   (mrow = warp&1 selects sample half; ncol = warp>>1 selects 16 cols).
// X fp16: 3-stage cp.async ring (pad-40 rows).
// W fp32: 2-stage cp.async ring (SW128-swizzled 256B rows); each thread
//   converts exactly the chunks it loaded -> sWc (2-stage, pad-72 rows).
// ONE __syncthreads per k-tile.
// ---------------------------------------------------------------------------
#define GN    64
#define PADX  40
#define PADW  72
#define XELEM (64*PADX)          // 2560 fp16 per stage
#define WCS   (32*PADW)          // 2304 fp16 per stage
// byte offsets
#define OX(s)   ((s)*(XELEM*2))                 // 3 x 5120
#define OWF(s)  (15360 + (s)*8192)              // 2 x 8192 (32x64 fp32 swizzled)
#define OWC(s)  (31744 + (s)*(WCS*2))           // 2 x 4608
#define SMEM_BYTES 40960

#define SWZ(o) ((o) ^ (((o) >> 3) & 0x70))

#define MMA_F16(d, a0,a1,a2,a3, b0,b1) \
  asm volatile("mma.sync.aligned.m16n8k16.row.col.f32.f16.f16.f32 " \
               "{%0,%1,%2,%3}, {%4,%5,%6,%7}, {%8,%9}, {%0,%1,%2,%3};" \
               : "+f"(d[0]),"+f"(d[1]),"+f"(d[2]),"+f"(d[3]) \
               : "r"(a0),"r"(a1),"r"(a2),"r"(a3),"r"(b0),"r"(b1))

#define LDSM_X4(r0,r1,r2,r3, addr) \
  asm volatile("ldmatrix.sync.aligned.m8n8.x4.shared.b16 {%0,%1,%2,%3}, [%4];" \
               : "=r"(r0),"=r"(r1),"=r"(r2),"=r"(r3) : "r"(addr))

#define LDSM_X2T(r0,r1, addr) \
  asm volatile("ldmatrix.sync.aligned.m8n8.x2.trans.shared.b16 {%0,%1}, [%2];" \
               : "=r"(r0),"=r"(r1) : "r"(addr))

#define CP16(sa, ga, sz) \
  asm volatile("cp.async.ca.shared.global [%0], [%1], 16, %2;" \
               :: "r"(sa), "l"(ga), "r"(sz))
#define CP16F(sa, ga) \
  asm volatile("cp.async.ca.shared.global [%0], [%1], 16;" :: "r"(sa), "l"(ga))
#define CP_COMMIT() asm volatile("cp.async.commit_group;" ::: "memory")

__global__ __launch_bounds__(256,4) void gemm_grouped(
    const __half* __restrict__ Xf,
    const float* __restrict__ W,
    const float* __restrict__ bias,
    float* __restrict__ Yf32,
    int K, int writeH)
{
    if ((int)blockIdx.y >= g_ngroups) return;

    extern __shared__ char smem[];
    uint32_t sb;
    asm("{ .reg .u64 t; cvta.to.shared.u64 t, %1; cvt.u32.u64 %0, t; }"
        : "=r"(sb) : "l"(smem));

    int slot = blockIdx.y;
    int cat  = g_gcat[slot];
    int s0 = g_gsamp[slot][0];
    int s1 = g_gsamp[slot][1];

    int n0 = blockIdx.x * GN;
    const float* Wg = W + (size_t)cat * K * HID;

    int tid  = threadIdx.x;
    int lane = tid & 31;
    int warp = tid >> 5;
    int mrow = warp & 1;      // sample half: rows mrow*32..+31
    int ncol = warp >> 1;     // 16-col slice: cols ncol*16..+15

    int lr15 = lane & 15;
    int hiK8 = ((lane >> 4) & 1) * 8;
    int mysamp = mrow ? s1 : s0;
    bool active = (mysamp >= 0);

    float acc[2][2][4];
    #pragma unroll
    for (int mt = 0; mt < 2; mt++)
        #pragma unroll
        for (int nt = 0; nt < 2; nt++)
            #pragma unroll
            for (int j = 0; j < 4; j++) acc[mt][nt][j] = 0.0f;

    // ---- staging geometry ----
    // X: 64 rows x 32 k fp16 = 256 x 16B chunks, 1/thread
    int xr = tid >> 2, xq = tid & 3;
    int xsp = (xr < 32) ? s0 : s1;
    uint32_t xsz = (xsp >= 0) ? 16 : 0;
    const __half* xg = (xsp >= 0)
        ? (Xf + (size_t)(xsp*32 + (xr & 31))*K + xq*8) : Xf;
    uint32_t xso = (uint32_t)(xr*(PADX*2) + xq*16);

    // W fp32: 32 k x 64 n = 512 x 16B chunks, 2/thread (swizzled 256B rows)
    int wk[2], wn[2];
    uint32_t wswz[2], cdst[2];
    #pragma unroll
    for (int c = 0; c < 2; c++) {
        int idx = c*256 + tid;
        wk[c] = idx >> 4; wn[c] = idx & 15;
        wswz[c] = SWZ((uint32_t)(wk[c]*256 + wn[c]*16));
        cdst[c] = (uint32_t)(wk[c]*(PADW*2) + wn[c]*8);
    }

    int NT = K >> 5;

    // ---- prologue: issue tiles 0 and 1 ----
    #pragma unroll
    for (int pi = 0; pi < 2; pi++) {
        CP16(sb + OX(pi) + xso, xg + pi*32, xsz);
        #pragma unroll
        for (int c = 0; c < 2; c++)
            CP16F(sb + OWF(pi) + wswz[c],
                  &Wg[(size_t)(pi*32 + wk[c])*HID + n0 + wn[c]*4]);
        CP_COMMIT();
    }

    #pragma unroll 1
    for (int it = 0; it < NT; it++) {
        int xs = it % 3;
        int cs = it & 1;

        if (it < NT - 1)
            asm volatile("cp.async.wait_group 1;" ::: "memory");
        else
            asm volatile("cp.async.wait_group 0;" ::: "memory");

        // convert own W chunks (tile it): fp32 swizzled -> fp16 pad-72
        #pragma unroll
        for (int c = 0; c < 2; c++) {
            const float* src = (const float*)(smem + OWF(cs) + wswz[c]);
            float4 v = *reinterpret_cast<const float4*>(src);
            __half2 h0 = __floats2half2_rn(v.x, v.y);
            __half2 h1 = __floats2half2_rn(v.z, v.w);
            uint32_t u0 = *reinterpret_cast<uint32_t*>(&h0);
            uint32_t u1 = *reinterpret_cast<uint32_t*>(&h1);
            asm volatile("st.shared.v2.b32 [%0], {%1,%2};"
                         :: "r"(sb + OWC(cs) + cdst[c]), "r"(u0), "r"(u1) : "memory");
        }
        __syncthreads();   // converts + all cp.async arrivals visible CTA-wide

        // prefetch tile it+2 (X stage (it+2)%3, W fp32 stage it%2 — freed above)
        if (it + 2 < NT) {
            int k0 = (it + 2) << 5;
            CP16(sb + OX((it + 2) % 3) + xso, xg + k0, xsz);
            #pragma unroll
            for (int c = 0; c < 2; c++)
                CP16F(sb + OWF(cs) + wswz[c],
                      &Wg[(size_t)(k0 + wk[c])*HID + n0 + wn[c]*4]);
            CP_COMMIT();
        }

        // compute tile it: warp 32x16, 2 k16 steps
        if (active) {
            #pragma unroll
            for (int ks = 0; ks < 2; ks++) {
                uint32_t a[2][4];
                #pragma unroll
                for (int mt = 0; mt < 2; mt++) {
                    uint32_t aoff = (uint32_t)(OX(xs)
                        + ((mrow*32 + mt*16 + lr15)*PADX + ks*16 + hiK8) * 2);
                    LDSM_X4(a[mt][0],a[mt][1],a[mt][2],a[mt][3], sb + aoff);
                }
                #pragma unroll
                for (int nt = 0; nt < 2; nt++) {
                    uint32_t boff = (uint32_t)(OWC(cs)
                        + ((ks*16 + lr15)*PADW + ncol*16 + nt*8) * 2);
                    uint32_t b0, b1;
                    LDSM_X2T(b0, b1, sb + boff);
                    #pragma unroll
                    for (int mt = 0; mt < 2; mt++)
                        MMA_F16(acc[mt][nt], a[mt][0],a[mt][1],a[mt][2],a[mt][3], b0,b1);
                }
            }
        }
    }

    // ---- epilogue ----
    if (!active) return;
    int r  = lane >> 2;
    int c2 = (lane & 3) * 2;
    #pragma unroll
    for (int mt = 0; mt < 2; mt++) {
        int grow0 = mysamp*32 + mt*16 + r;
        #pragma unroll
        for (int nt = 0; nt < 2; nt++) {
            int col = n0 + ncol*16 + nt*8 + c2;
            float2 bv = *reinterpret_cast<const float2*>(&bias[(size_t)cat*HID + col]);
            float y0 = acc[mt][nt][0] + bv.x;
            float y1 = acc[mt][nt][1] + bv.y;
            float y2 = acc[mt][nt][2] + bv.x;
            float y3 = acc[mt][nt][3] + bv.y;
            if (writeH) {
                y0 = y0 / (1.0f + __expf(-y0));
                y1 = y1 / (1.0f + __expf(-y1));
                y2 = y2 / (1.0f + __expf(-y2));
                y3 = y3 / (1.0f + __expf(-y3));
                __half2 p01 = __floats2half2_rn(y0, y1);
                __half2 p23 = __floats2half2_rn(y2, y3);
                *reinterpret_cast<uint32_t*>(&g_hf[(size_t)grow0*HID + col])
                    = *reinterpret_cast<uint32_t*>(&p01);
                *reinterpret_cast<uint32_t*>(&g_hf[(size_t)(grow0+8)*HID + col])
                    = *reinterpret_cast<uint32_t*>(&p23);
            } else {
                float2 o01 = {y0, y1};
                float2 o23 = {y2, y3};
                *reinterpret_cast<float2*>(&Yf32[(size_t)grow0*HID + col]) = o01;
                *reinterpret_cast<float2*>(&Yf32[(size_t)(grow0+8)*HID + col]) = o23;
            }
        }
    }
}

// ---------------------------------------------------------------------------
extern "C" void kernel_launch(void* const* d_in, const int* in_sizes, int n_in,
                              void* d_out, int out_size)
{
    const float* actions   = (const float*)d_in[0];
    const int*   timesteps = (const int*)  d_in[1];
    const int*   cat_ids   = (const int*)  d_in[2];
    const float* W1        = (const float*)d_in[3];
    const float* b1        = (const float*)d_in[4];
    const float* W2        = (const float*)d_in[5];
    const float* b2        = (const float*)d_in[6];
    const float* W3        = (const float*)d_in[7];
    const float* b3        = (const float*)d_in[8];
    float* out = (float*)d_out;

    __half *xf, *hf;
    cudaGetSymbolAddress((void**)&xf, g_xf);
    cudaGetSymbolAddress((void**)&hf, g_hf);

    static bool attr_set = false;
    if (!attr_set) {
        cudaFuncSetAttribute(gemm_grouped,
                             cudaFuncAttributeMaxDynamicSharedMemorySize, SMEM_BYTES);
        attr_set = true;
    }

    setup_groups<<<1, 32>>>(cat_ids);
    embed_kernel<<<dim3(BB, 3), 256>>>(actions, timesteps, cat_ids, W1, b1);

    // h = swish(x @ W2[cat] + b2) -> fp16
    gemm_grouped<<<dim3(HID/GN, 32), 256, SMEM_BYTES>>>(xf, W2, b2, nullptr, K2, 1);

    // out = h @ W3[cat] + b3 -> fp32
    gemm_grouped<<<dim3(HID/GN, 32), 256, SMEM_BYTES>>>(hf, W3, b3, out, HID, 0);
}